// round 7
// baseline (speedup 1.0000x reference)
#include <cuda_runtime.h>
#include <cuda_fp16.h>

#define BB   256
#define TT   512
#define HH   128
#define G4   512
#define IND  10
#define TRG  32

typedef unsigned long long u64;

// ---------------- packed f32x2 helpers ----------------
__device__ __forceinline__ void ffma2(u64& acc, u64 a, u64 b) {
    asm("fma.rn.f32x2 %0, %1, %2, %0;" : "+l"(acc) : "l"(a), "l"(b));
}
__device__ __forceinline__ u64 pk(float lo, float hi) {
    u64 d; asm("mov.b64 %0, {%1, %2};" : "=l"(d) : "f"(lo), "f"(hi)); return d;
}
__device__ __forceinline__ float psum(u64 a) {
    float x, y; asm("mov.b64 {%0, %1}, %2;" : "=f"(x), "=f"(y) : "l"(a));
    return x + y;
}
__device__ __forceinline__ u64 h2u64(unsigned int h2bits) {
    __half2 h = *reinterpret_cast<__half2*>(&h2bits);
    float2 f = __half22float2(h);
    u64 d; asm("mov.b64 %0, {%1, %2};" : "=l"(d) : "f"(f.x), "f"(f.y)); return d;
}

// ---------------- device-global scratch ----------------
// w_hh fp16 packed k-pairs for register residency:
//   g_whh16h[((L*64 + (k>>1))*512 + g)*2 + (k&1)] = w_hh_L[g*128 + k]
// -> thread g LDGs u32 j at [(L*64+j)*512+g]: coalesced across lanes.
__device__ __half g_whh16h[2 * 64 * 512 * 2];
__device__ __half g_wih1h[G4 * HH];               // fp16 blocked, xgate1 only
__device__ float  g_h1[(size_t)BB * TT * HH];
__device__ float  g_xg1[(size_t)BB * TT * G4];
__device__ float  g_h2last[BB * HH];

__global__ void prep_kernel(const float* __restrict__ w_hh0,
                            const float* __restrict__ w_hh1,
                            const float* __restrict__ w_ih1)
{
    int idx = blockIdx.x * blockDim.x + threadIdx.x;   // 196608 threads
    if (idx < 131072) {
        int L = idx >> 16;
        int e = idx & 65535;
        int g = e >> 7;
        int k = e & 127;
        float v = (L ? w_hh1 : w_hh0)[e];
        g_whh16h[(((L * 64 + (k >> 1)) * 512 + g) << 1) + (k & 1)] = __float2half(v);
    } else {
        int e = idx - 131072;
        int g = e >> 7;
        int k = e & 127;
        int dst = ((k >> 3) << 12) + (g << 3) + (k & 7);
        g_wih1h[dst] = __float2half(w_ih1[e]);
    }
}

__device__ __forceinline__ float sigf(float x) {
    return 1.0f / (1.0f + __expf(-x));
}
__device__ __forceinline__ float tanhfast(float x) {
    return 2.0f / (1.0f + __expf(-2.0f * x)) - 1.0f;
}

// ---------------- LSTM recurrence ----------------
// 128 CTAs x 2 batch rows, 512 threads (16 warps = 4/SMSP).
// Thread = gate tid, both rows. ALL w_hh fp16 in 64 u32 REGISTERS ->
// zero weight smem traffic, ~104 regs (no spill), crossbar = h broadcast only.
// smem (bytes):
//   [0,20480)        wih0 fp32 k-major [10][512]   (layer0 only)
//   [20480,22528)    bias [512]                    (layer0 only)
//   [22528,23552)    hs [2 rows][128]
//   [23552,27648)    gs [2 rows][512]
//   [27648,27776)    xs [2 rows][16]               (layer0 only)
#define LSTM_SMEM 27776

template<int LAYER>
__global__ void __launch_bounds__(512, 1) lstm_layer_kernel(
    const float* __restrict__ x,
    const float* __restrict__ w_ih,
    const float* __restrict__ b_ih,
    const float* __restrict__ b_hh)
{
    extern __shared__ char smem[];
    float* wih_s  = (float*)smem;
    float* bias_s = (float*)(smem + 20480);
    float* hs     = (float*)(smem + 22528);
    float* gs     = (float*)(smem + 23552);
    float* xs     = (float*)(smem + 27648);

    const int tid = threadIdx.x;        // = gate index
    const int bb  = blockIdx.x;

    // whole w_hh row (128 k, fp16) into 64 u32 registers, coalesced LDG
    unsigned int wu[64];
    {
        const unsigned int* wg = (const unsigned int*)g_whh16h + LAYER * 64 * 512;
        #pragma unroll
        for (int i = 0; i < 64; i++)
            wu[i] = wg[i * 512 + tid];
    }

    if (LAYER == 0) {
        #pragma unroll
        for (int j = 0; j < IND; j++)
            wih_s[j * 512 + tid] = w_ih[tid * IND + j];
        bias_s[tid] = b_ih[tid] + b_hh[tid];
    }
    if (tid < 256) hs[tid] = 0.0f;

    float creg = 0.0f;                  // cell state: act thread = (row, unit)
    const int r_act = tid >> 7;
    const int j_act = tid & 127;

    // prefetch t=0 step inputs
    float xg0 = 0.0f, xg1v = 0.0f;
    int xr = 0, xj = 0;
    if (LAYER == 0) {
        if (tid < 2 * IND) {
            xr = tid / IND; xj = tid - xr * IND;
            xs[xr * 16 + xj] = x[(size_t)(2 * bb + xr) * (TT * IND) + xj];
        }
    } else {
        xg0  = g_xg1[((size_t)(2 * bb + 0) * TT + 0) * G4 + tid];
        xg1v = g_xg1[((size_t)(2 * bb + 1) * TT + 0) * G4 + tid];
    }
    __syncthreads();

    const ulonglong2* h0v = (const ulonglong2*)hs;          // row0: 4 floats / load
    const ulonglong2* h1v = (const ulonglong2*)(hs + 128);  // row1

    for (int t = 0; t < TT; t++) {
        // [A] prefetch next step's inputs (hidden behind matmul)
        float nx = 0.0f, n0 = 0.0f, n1 = 0.0f;
        if (LAYER == 0) {
            if (tid < 2 * IND && t + 1 < TT)
                nx = x[(size_t)(2 * bb + xr) * (TT * IND) + (size_t)(t + 1) * IND + xj];
        } else {
            if (t + 1 < TT) {
                n0 = g_xg1[((size_t)(2 * bb + 0) * TT + (t + 1)) * G4 + tid];
                n1 = g_xg1[((size_t)(2 * bb + 1) * TT + (t + 1)) * G4 + tid];
            }
        }

        // [B] initial scalar part (bias + x-projection for layer0)
        float i0, i1;
        if (LAYER == 0) {
            float bv = bias_s[tid];
            i0 = bv; i1 = bv;
            #pragma unroll
            for (int j = 0; j < IND; j++) {
                float wv = wih_s[j * 512 + tid];
                i0 = fmaf(xs[j],      wv, i0);
                i1 = fmaf(xs[16 + j], wv, i1);
            }
        } else {
            i0 = xg0; i1 = xg1v;
        }

        u64 a0a = pk(i0, 0.0f), a0b = pk(0.0f, 0.0f);
        u64 a1a = pk(i1, 0.0f), a1b = pk(0.0f, 0.0f);

        // full 128-k dot: weights from registers (cvt fp16->fp32 on alu pipe),
        // h via 16B broadcast LDS. No weight smem traffic at all.
        #pragma unroll
        for (int j = 0; j < 32; j++) {
            u64 w0 = h2u64(wu[2 * j]);       // k = 4j, 4j+1
            u64 w1 = h2u64(wu[2 * j + 1]);   // k = 4j+2, 4j+3
            ulonglong2 h0 = h0v[j];
            ulonglong2 h1 = h1v[j];
            ffma2(a0a, h0.x, w0);
            ffma2(a0b, h0.y, w1);
            ffma2(a1a, h1.x, w0);
            ffma2(a1b, h1.y, w1);
        }

        gs[tid]       = psum(a0a) + psum(a0b);
        gs[512 + tid] = psum(a1a) + psum(a1b);
        __syncthreads();

        // [C] activations + state update (threads 0..255)
        if (tid < 256) {
            const float* gr = gs + r_act * 512;
            float iv = sigf(gr[j_act]);
            float fv = sigf(gr[128 + j_act]);
            float gv = tanhfast(gr[256 + j_act]);
            float ov = sigf(gr[384 + j_act]);
            creg = fv * creg + iv * gv;
            float hn = ov * tanhfast(creg);
            hs[r_act * 128 + j_act] = hn;
            if (LAYER == 0) {
                g_h1[((size_t)(2 * bb + r_act) * TT + t) * HH + j_act] = hn;
            } else if (t == TT - 1) {
                g_h2last[(2 * bb + r_act) * HH + j_act] = hn;
            }
        }
        if (LAYER == 0) {
            if (tid < 2 * IND) xs[xr * 16 + xj] = nx;
        } else {
            xg0 = n0; xg1v = n1;
        }
        __syncthreads();
    }
}

// ---------------- layer-1 input projection GEMM (unchanged from R4) ----------------
#define XG_SMEM (131072 + TRG * HH * 4)

__global__ void __launch_bounds__(512, 1) xgate1_kernel(
    const float* __restrict__ b_ih1, const float* __restrict__ b_hh1)
{
    extern __shared__ char smem[];
    __half* wsm = (__half*)smem;
    float*  h_s = (float*)(smem + 131072);

    const int tid = threadIdx.x;

    uint4*       wsm4 = (uint4*)wsm;
    const uint4* gw4  = (const uint4*)g_wih1h;
    #pragma unroll
    for (int i = 0; i < 16; i++)
        wsm4[i * 512 + tid] = gw4[i * 512 + tid];

    const size_t base = (size_t)blockIdx.x * TRG * HH;
    float4*       h_s4 = (float4*)h_s;
    const float4* src4 = (const float4*)(g_h1 + base);
    #pragma unroll
    for (int i = 0; i < (TRG * HH / 4) / 512; i++)
        h_s4[i * 512 + tid] = src4[i * 512 + tid];
    __syncthreads();

    float bv = b_ih1[tid] + b_hh1[tid];
    u64 acc[TRG];
    #pragma unroll
    for (int r = 0; r < TRG; r++) acc[r] = pk(bv, 0.0f);

    #pragma unroll 1
    for (int c = 0; c < 16; c++) {
        uint4 wp = wsm4[c * 512 + tid];
        u64 w0 = h2u64(wp.x);
        u64 w1 = h2u64(wp.y);
        u64 w2 = h2u64(wp.z);
        u64 w3 = h2u64(wp.w);
        #pragma unroll
        for (int r = 0; r < TRG; r++) {
            ulonglong2 ha = *(const ulonglong2*)(h_s + r * HH + c * 8);
            ulonglong2 hb = *(const ulonglong2*)(h_s + r * HH + c * 8 + 4);
            ffma2(acc[r], ha.x, w0);
            ffma2(acc[r], ha.y, w1);
            ffma2(acc[r], hb.x, w2);
            ffma2(acc[r], hb.y, w3);
        }
    }

    #pragma unroll
    for (int r = 0; r < TRG; r++)
        g_xg1[((size_t)blockIdx.x * TRG + r) * G4 + tid] = psum(acc[r]);
}

// ---------------- final FC ----------------
__global__ void fc_kernel(const float* __restrict__ fc_w,
                          const float* __restrict__ fc_b,
                          float* __restrict__ out)
{
    int b = threadIdx.x;
    const float* hrow = g_h2last + b * HH;
    #pragma unroll
    for (int c = 0; c < 10; c++) {
        float acc = fc_b[c];
        #pragma unroll
        for (int k = 0; k < HH; k++)
            acc = fmaf(hrow[k], fc_w[c * HH + k], acc);
        out[b * 10 + c] = acc;
    }
}

extern "C" void kernel_launch(void* const* d_in, const int* in_sizes, int n_in,
                              void* d_out, int out_size)
{
    const float* x     = (const float*)d_in[0];
    const float* w_ih0 = (const float*)d_in[1];
    const float* w_hh0 = (const float*)d_in[2];
    const float* b_ih0 = (const float*)d_in[3];
    const float* b_hh0 = (const float*)d_in[4];
    const float* w_ih1 = (const float*)d_in[5];
    const float* w_hh1 = (const float*)d_in[6];
    const float* b_ih1 = (const float*)d_in[7];
    const float* b_hh1 = (const float*)d_in[8];
    const float* fc_w  = (const float*)d_in[9];
    const float* fc_b  = (const float*)d_in[10];
    float* out = (float*)d_out;

    cudaFuncSetAttribute(xgate1_kernel,
                         cudaFuncAttributeMaxDynamicSharedMemorySize, XG_SMEM);

    prep_kernel<<<768, 256>>>(w_hh0, w_hh1, w_ih1);
    lstm_layer_kernel<0><<<BB / 2, 512, LSTM_SMEM>>>(x, w_ih0, b_ih0, b_hh0);
    xgate1_kernel<<<(BB * TT) / TRG, 512, XG_SMEM>>>(b_ih1, b_hh1);
    lstm_layer_kernel<1><<<BB / 2, 512, LSTM_SMEM>>>(nullptr, nullptr, nullptr, nullptr);
    fc_kernel<<<1, 256>>>(fc_w, fc_b, out);
}

// round 8
// speedup vs baseline: 2.0070x; 2.0070x over previous
#include <cuda_runtime.h>
#include <cuda_fp16.h>

#define BB   256
#define TT   512
#define HH   128
#define G4   512
#define IND  10
#define TRG  32

typedef unsigned long long u64;

// ---------------- packed f32x2 helpers ----------------
__device__ __forceinline__ void ffma2(u64& acc, u64 a, u64 b) {
    asm("fma.rn.f32x2 %0, %1, %2, %0;" : "+l"(acc) : "l"(a), "l"(b));
}
__device__ __forceinline__ u64 pk(float lo, float hi) {
    u64 d; asm("mov.b64 %0, {%1, %2};" : "=l"(d) : "f"(lo), "f"(hi)); return d;
}
__device__ __forceinline__ float psum(u64 a) {
    float x, y; asm("mov.b64 {%0, %1}, %2;" : "=f"(x), "=f"(y) : "l"(a));
    return x + y;
}
__device__ __forceinline__ u64 h2u64(unsigned int h2bits) {
    __half2 h = *reinterpret_cast<__half2*>(&h2bits);
    float2 f = __half22float2(h);
    u64 d; asm("mov.b64 %0, {%1, %2};" : "=l"(d) : "f"(f.x), "f"(f.y)); return d;
}

// ---------------- device-global scratch ----------------
__device__ __half g_whh0h[G4 * HH];               // layer0 w_hh, fp16, k-blocked
__device__ __half g_whh1h[G4 * HH];               // layer1 w_hh, fp16, k-blocked
__device__ __half g_wih1h[G4 * HH];               // layer1 w_ih, fp16, k-blocked
__device__ float  g_h1[(size_t)BB * TT * HH];
__device__ float  g_xg1[(size_t)BB * TT * G4];
__device__ float  g_h2last[BB * HH];

// Blocked fp16 layout: dst[(k>>3)*4096 + g*8 + (k&7)] = w[g*128 + k].
__global__ void prep_kernel(const float* __restrict__ w_hh0,
                            const float* __restrict__ w_hh1,
                            const float* __restrict__ w_ih1)
{
    int idx = blockIdx.x * blockDim.x + threadIdx.x;
    if (idx >= 3 * G4 * HH) return;
    int m = idx >> 16;
    int e = idx & 65535;
    int g = e >> 7;
    int k = e & 127;
    int dst = ((k >> 3) << 12) + (g << 3) + (k & 7);
    const float* s = (m == 0) ? w_hh0 : (m == 1 ? w_hh1 : w_ih1);
    __half*      d = (m == 0) ? g_whh0h : (m == 1 ? g_whh1h : g_wih1h);
    d[dst] = __float2half(s[e]);
}

__device__ __forceinline__ float sigf(float x) {
    return 1.0f / (1.0f + __expf(-x));
}
__device__ __forceinline__ float tanhfast(float x) {
    return 2.0f / (1.0f + __expf(-2.0f * x)) - 1.0f;
}

// ---------------- LSTM recurrence (EXACT R4 version — best known) ----------------
// 128 CTAs x 2 batch rows, 256 threads; thread computes gates {tid, tid+256}
// for both rows. k<64: fp32 weights in registers. k in [64,128): fp16 in smem.
#define LSTM_SMEM 93312

template<int LAYER>
__global__ void __launch_bounds__(256, 1) lstm_layer_kernel(
    const float* __restrict__ x,
    const float* __restrict__ w_ih,
    const float* __restrict__ w_hh,
    const float* __restrict__ b_ih,
    const float* __restrict__ b_hh)
{
    extern __shared__ char smem[];
    __half* wsm    = (__half*)smem;
    float*  wih_s  = (float*)(smem + 65536);
    float*  bias_s = (float*)(smem + 86016);
    float*  hs     = (float*)(smem + 88064);
    float*  gs     = (float*)(smem + 89088);
    float*  xs     = (float*)(smem + 93184);

    const int tid = threadIdx.x;
    const int bb  = blockIdx.x;
    const int g0  = tid;
    const int g1  = tid + 256;

    u64 wreg0[32], wreg1[32];
    {
        const u64* wa = (const u64*)(w_hh + (size_t)g0 * HH);
        const u64* wb = (const u64*)(w_hh + (size_t)g1 * HH);
        #pragma unroll
        for (int i = 0; i < 32; i++) { wreg0[i] = wa[i]; wreg1[i] = wb[i]; }
    }

    uint4*       wsm4 = (uint4*)wsm;
    const uint4* gw4  = (const uint4*)((LAYER == 0) ? g_whh0h : g_whh1h);
    #pragma unroll
    for (int i = 0; i < 8; i++) {
        wsm4[i * 512 + g0] = gw4[(i + 8) * 512 + g0];
        wsm4[i * 512 + g1] = gw4[(i + 8) * 512 + g1];
    }

    if (LAYER == 0) {
        for (int i = tid; i < G4 * IND; i += 256) {
            int g = i / IND, j = i - g * IND;
            wih_s[j * 512 + g] = w_ih[i];
        }
        bias_s[g0] = b_ih[g0] + b_hh[g0];
        bias_s[g1] = b_ih[g1] + b_hh[g1];
    }
    hs[tid] = 0.0f;

    float creg = 0.0f;
    const int r_act = tid >> 7;
    const int j_act = tid & 127;

    float xg00 = 0.0f, xg01 = 0.0f, xg10 = 0.0f, xg11 = 0.0f;
    int xr = 0, xj = 0;
    if (LAYER == 0) {
        if (tid < 2 * IND) {
            xr = tid / IND; xj = tid - xr * IND;
            xs[xr * 16 + xj] = x[(size_t)(2 * bb + xr) * (TT * IND) + xj];
        }
    } else {
        const float* p0 = g_xg1 + ((size_t)(2 * bb + 0) * TT + 0) * G4;
        const float* p1 = g_xg1 + ((size_t)(2 * bb + 1) * TT + 0) * G4;
        xg00 = p0[g0]; xg01 = p0[g1];
        xg10 = p1[g0]; xg11 = p1[g1];
    }
    __syncthreads();

    const ulonglong2* h0v = (const ulonglong2*)hs;
    const ulonglong2* h1v = (const ulonglong2*)(hs + 128);

    for (int t = 0; t < TT; t++) {
        float nx = 0.0f, n00 = 0.0f, n01 = 0.0f, n10 = 0.0f, n11 = 0.0f;
        if (LAYER == 0) {
            if (tid < 2 * IND && t + 1 < TT)
                nx = x[(size_t)(2 * bb + xr) * (TT * IND) + (size_t)(t + 1) * IND + xj];
        } else {
            if (t + 1 < TT) {
                const float* p0 = g_xg1 + ((size_t)(2 * bb + 0) * TT + (t + 1)) * G4;
                const float* p1 = g_xg1 + ((size_t)(2 * bb + 1) * TT + (t + 1)) * G4;
                n00 = p0[g0]; n01 = p0[g1];
                n10 = p1[g0]; n11 = p1[g1];
            }
        }

        float i00, i01, i10, i11;
        if (LAYER == 0) {
            float bv0 = bias_s[g0], bv1 = bias_s[g1];
            i00 = bv0; i01 = bv1; i10 = bv0; i11 = bv1;
            #pragma unroll
            for (int j = 0; j < IND; j++) {
                float w0 = wih_s[j * 512 + g0];
                float w1 = wih_s[j * 512 + g1];
                float x0 = xs[j], x1 = xs[16 + j];
                i00 = fmaf(x0, w0, i00);
                i01 = fmaf(x0, w1, i01);
                i10 = fmaf(x1, w0, i10);
                i11 = fmaf(x1, w1, i11);
            }
        } else {
            i00 = xg00; i01 = xg01; i10 = xg10; i11 = xg11;
        }

        u64 a00a = pk(i00, 0.0f), a00b = pk(0.0f, 0.0f);
        u64 a01a = pk(i10, 0.0f), a01b = pk(0.0f, 0.0f);
        u64 a10a = pk(i01, 0.0f), a10b = pk(0.0f, 0.0f);
        u64 a11a = pk(i11, 0.0f), a11b = pk(0.0f, 0.0f);

        #pragma unroll
        for (int i = 0; i < 16; i++) {
            ulonglong2 h0 = h0v[i];
            ulonglong2 h1 = h1v[i];
            ffma2(a00a, h0.x, wreg0[2 * i]);
            ffma2(a00b, h0.y, wreg0[2 * i + 1]);
            ffma2(a01a, h1.x, wreg0[2 * i]);
            ffma2(a01b, h1.y, wreg0[2 * i + 1]);
            ffma2(a10a, h0.x, wreg1[2 * i]);
            ffma2(a10b, h0.y, wreg1[2 * i + 1]);
            ffma2(a11a, h1.x, wreg1[2 * i]);
            ffma2(a11b, h1.y, wreg1[2 * i + 1]);
        }

        #pragma unroll
        for (int c = 0; c < 8; c++) {
            uint4 wpA = wsm4[c * 512 + g0];
            uint4 wpB = wsm4[c * 512 + g1];
            u64 wA0 = h2u64(wpA.x), wA1 = h2u64(wpA.y);
            u64 wA2 = h2u64(wpA.z), wA3 = h2u64(wpA.w);
            u64 wB0 = h2u64(wpB.x), wB1 = h2u64(wpB.y);
            u64 wB2 = h2u64(wpB.z), wB3 = h2u64(wpB.w);
            ulonglong2 ha = h0v[16 + 2 * c];
            ulonglong2 hb = h0v[16 + 2 * c + 1];
            ulonglong2 ka = h1v[16 + 2 * c];
            ulonglong2 kb = h1v[16 + 2 * c + 1];
            ffma2(a00a, ha.x, wA0); ffma2(a00b, ha.y, wA1);
            ffma2(a00a, hb.x, wA2); ffma2(a00b, hb.y, wA3);
            ffma2(a01a, ka.x, wA0); ffma2(a01b, ka.y, wA1);
            ffma2(a01a, kb.x, wA2); ffma2(a01b, kb.y, wA3);
            ffma2(a10a, ha.x, wB0); ffma2(a10b, ha.y, wB1);
            ffma2(a10a, hb.x, wB2); ffma2(a10b, hb.y, wB3);
            ffma2(a11a, ka.x, wB0); ffma2(a11b, ka.y, wB1);
            ffma2(a11a, kb.x, wB2); ffma2(a11b, kb.y, wB3);
        }

        gs[g0]       = psum(a00a) + psum(a00b);
        gs[g1]       = psum(a10a) + psum(a10b);
        gs[512 + g0] = psum(a01a) + psum(a01b);
        gs[512 + g1] = psum(a11a) + psum(a11b);
        __syncthreads();

        {
            const float* gr = gs + r_act * 512;
            float iv = sigf(gr[j_act]);
            float fv = sigf(gr[128 + j_act]);
            float gv = tanhfast(gr[256 + j_act]);
            float ov = sigf(gr[384 + j_act]);
            creg = fv * creg + iv * gv;
            float hn = ov * tanhfast(creg);
            hs[r_act * 128 + j_act] = hn;
            if (LAYER == 0) {
                g_h1[((size_t)(2 * bb + r_act) * TT + t) * HH + j_act] = hn;
            } else if (t == TT - 1) {
                g_h2last[(2 * bb + r_act) * HH + j_act] = hn;
            }
        }
        if (LAYER == 0) {
            if (tid < 2 * IND) xs[xr * 16 + xj] = nx;
        } else {
            xg00 = n00; xg01 = n01; xg10 = n10; xg11 = n11;
        }
        __syncthreads();
    }
}

// ---------------- layer-1 input projection GEMM (NEW: 2 gates/thread) ----------------
// 256 threads; thread = gates (tid, tid+256); TRG=32 rows/CTA.
// Crossbar: h-broadcast halves vs thread-per-gate; FMA-bound by model.
// regs: 64 u64 acc (128) + w temps (16) + misc ~30 => ~175 < 255, no spill.
#define XG_SMEM (131072 + TRG * HH * 4)

__global__ void __launch_bounds__(256, 1) xgate1_kernel(
    const float* __restrict__ b_ih1, const float* __restrict__ b_hh1)
{
    extern __shared__ char smem[];
    __half* wsm = (__half*)smem;
    float*  h_s = (float*)(smem + 131072);

    const int tid = threadIdx.x;
    const int g0t = tid;
    const int g1t = tid + 256;

    uint4*       wsm4 = (uint4*)wsm;
    const uint4* gw4  = (const uint4*)g_wih1h;
    #pragma unroll
    for (int i = 0; i < 16; i++) {
        wsm4[i * 512 + g0t] = gw4[i * 512 + g0t];
        wsm4[i * 512 + g1t] = gw4[i * 512 + g1t];
    }

    const size_t base = (size_t)blockIdx.x * TRG * HH;
    float4*       h_s4 = (float4*)h_s;
    const float4* src4 = (const float4*)(g_h1 + base);
    #pragma unroll
    for (int i = 0; i < (TRG * HH / 4) / 256; i++)
        h_s4[i * 256 + tid] = src4[i * 256 + tid];
    __syncthreads();

    float bvA = b_ih1[g0t] + b_hh1[g0t];
    float bvB = b_ih1[g1t] + b_hh1[g1t];
    u64 accA[TRG], accB[TRG];
    #pragma unroll
    for (int r = 0; r < TRG; r++) { accA[r] = pk(bvA, 0.0f); accB[r] = pk(bvB, 0.0f); }

    #pragma unroll 1
    for (int c = 0; c < 16; c++) {
        uint4 wpA = wsm4[c * 512 + g0t];
        uint4 wpB = wsm4[c * 512 + g1t];
        u64 wA0 = h2u64(wpA.x), wA1 = h2u64(wpA.y);
        u64 wA2 = h2u64(wpA.z), wA3 = h2u64(wpA.w);
        u64 wB0 = h2u64(wpB.x), wB1 = h2u64(wpB.y);
        u64 wB2 = h2u64(wpB.z), wB3 = h2u64(wpB.w);
        #pragma unroll
        for (int r = 0; r < TRG; r++) {
            ulonglong2 ha = *(const ulonglong2*)(h_s + r * HH + c * 8);
            ulonglong2 hb = *(const ulonglong2*)(h_s + r * HH + c * 8 + 4);
            ffma2(accA[r], ha.x, wA0);
            ffma2(accA[r], ha.y, wA1);
            ffma2(accA[r], hb.x, wA2);
            ffma2(accA[r], hb.y, wA3);
            ffma2(accB[r], ha.x, wB0);
            ffma2(accB[r], ha.y, wB1);
            ffma2(accB[r], hb.x, wB2);
            ffma2(accB[r], hb.y, wB3);
        }
    }

    #pragma unroll
    for (int r = 0; r < TRG; r++) {
        g_xg1[((size_t)blockIdx.x * TRG + r) * G4 + g0t] = psum(accA[r]);
        g_xg1[((size_t)blockIdx.x * TRG + r) * G4 + g1t] = psum(accB[r]);
    }
}

// ---------------- final FC ----------------
__global__ void fc_kernel(const float* __restrict__ fc_w,
                          const float* __restrict__ fc_b,
                          float* __restrict__ out)
{
    int b = threadIdx.x;
    const float* hrow = g_h2last + b * HH;
    #pragma unroll
    for (int c = 0; c < 10; c++) {
        float acc = fc_b[c];
        #pragma unroll
        for (int k = 0; k < HH; k++)
            acc = fmaf(hrow[k], fc_w[c * HH + k], acc);
        out[b * 10 + c] = acc;
    }
}

extern "C" void kernel_launch(void* const* d_in, const int* in_sizes, int n_in,
                              void* d_out, int out_size)
{
    const float* x     = (const float*)d_in[0];
    const float* w_ih0 = (const float*)d_in[1];
    const float* w_hh0 = (const float*)d_in[2];
    const float* b_ih0 = (const float*)d_in[3];
    const float* b_hh0 = (const float*)d_in[4];
    const float* w_ih1 = (const float*)d_in[5];
    const float* w_hh1 = (const float*)d_in[6];
    const float* b_ih1 = (const float*)d_in[7];
    const float* b_hh1 = (const float*)d_in[8];
    const float* fc_w  = (const float*)d_in[9];
    const float* fc_b  = (const float*)d_in[10];
    float* out = (float*)d_out;

    cudaFuncSetAttribute(lstm_layer_kernel<0>,
                         cudaFuncAttributeMaxDynamicSharedMemorySize, LSTM_SMEM);
    cudaFuncSetAttribute(lstm_layer_kernel<1>,
                         cudaFuncAttributeMaxDynamicSharedMemorySize, LSTM_SMEM);
    cudaFuncSetAttribute(xgate1_kernel,
                         cudaFuncAttributeMaxDynamicSharedMemorySize, XG_SMEM);

    prep_kernel<<<768, 256>>>(w_hh0, w_hh1, w_ih1);
    lstm_layer_kernel<0><<<BB / 2, 256, LSTM_SMEM>>>(x, w_ih0, w_hh0, b_ih0, b_hh0);
    xgate1_kernel<<<(BB * TT) / TRG, 256, XG_SMEM>>>(b_ih1, b_hh1);
    lstm_layer_kernel<1><<<BB / 2, 256, LSTM_SMEM>>>(nullptr, nullptr, w_hh1, nullptr, nullptr);
    fc_kernel<<<1, 256>>>(fc_w, fc_b, out);
}